// round 2
// baseline (speedup 1.0000x reference)
#include <cuda_runtime.h>
#include <cstdint>

#define NFACES 1000
#define IMG    256
#define SPLIT  16
#define CHUNK  64                 // faces per chunk (16*64 = 1024 >= 1000)
#define EPSF   1e-6f
#define KEEP_T 30.0f              // sigmoid < 2^-30 < 2^-25 -> (1-frag)==1.0f exactly

__device__ float    g_part[SPLIT * IMG * IMG];  // per-chunk partial products (4 MB)
__device__ float    g_row[IMG];                 // per-tile loss sums
__device__ unsigned g_tcnt[IMG];                // per-tile chunk-completion counters (wrap -> replay-safe)
__device__ unsigned g_done;                     // tile-completion counter

__device__ __forceinline__ float ex2f(float x) {
    float y; asm("ex2.approx.f32 %0, %1;" : "=f"(y) : "f"(x)); return y;
}
__device__ __forceinline__ float rcpaf(float x) {
    float y; asm("rcp.approx.f32 %0, %1;" : "=f"(y) : "f"(x)); return y;
}

// ---------------------------------------------------------------------------
// Single fused kernel: grid (16, 16, SPLIT), 256 threads.
//   Phase A: threads 0..63 compute this chunk's 64 face edge-coefficients
//            (redundant per tile; inputs are L2-resident) + tile-level cull
//   Phase B: per-pixel partial soft-OR product over surviving faces -> g_part
//   Phase C: last chunk-block per tile combines 16 planes -> tile loss
//   Phase D: last tile sums 256 tile losses -> out[0]
// ---------------------------------------------------------------------------
__global__ void __launch_bounds__(256) fused_kernel(
    const float* __restrict__ verts,   // (1, V, 3)
    const int*   __restrict__ faces,   // (1, F, 3)
    const float* __restrict__ cam,     // (3,)
    const float* __restrict__ ref,     // (1, 256, 256)
    float*       __restrict__ out)
{
    __shared__ float4 sA[CHUNK], sB[CHUNK];
    __shared__ float  sC[CHUNK];
    __shared__ int    wcnt[2];
    __shared__ int    s_flag;
    __shared__ float  red[256];

    const int tid  = threadIdx.x;
    const int lane = tid & 31, wid = tid >> 5;
    const int c0 = blockIdx.x * 16, r0 = blockIdx.y * 16;
    const int tileIdx = blockIdx.y * 16 + blockIdx.x;
    const int z = blockIdx.z;

    // tile pixel-center bounds (y decreases with row)
    const float xmin = (2.f * c0 + 1.f)        * (1.f / 256.f) - 1.f;
    const float xmax = (2.f * (c0 + 15) + 1.f) * (1.f / 256.f) - 1.f;
    const float ymax = 1.f - (2.f * r0 + 1.f)        * (1.f / 256.f);
    const float ymin = 1.f - (2.f * (r0 + 15) + 1.f) * (1.f / 256.f);

    // ---------------- Phase A: in-block prep + cull (threads 0..63) --------
    bool keep = false;
    float4 fa = make_float4(0,0,0,0), fb = make_float4(0,0,0,0);
    float  fc = 0.f;

    if (tid < CHUNK) {
        int f = z * CHUNK + tid;
        if (f < NFACES) {
            float ex = cam[0], ey = cam[1], ez = cam[2];

            // camera basis (z = normalize(-eye), up = (0,1,0))
            float zx = -ex, zy = -ey, zz = -ez;
            float zn = sqrtf(zx*zx + zy*zy + zz*zz) + EPSF;
            zx /= zn; zy /= zn; zz /= zn;
            float xx = zz, xz = -zx;
            float xn = sqrtf(xx*xx + xz*xz) + EPSF;
            xx /= xn; xz /= xn;
            float yx = zy * xz;
            float yy = zz * xx - zx * xz;
            float yz = -zy * xx;

            const float w = 0.57735026918962576f;  // tan(30 deg)

            float px[3], py[3];
            #pragma unroll
            for (int k = 0; k < 3; k++) {
                int vi = faces[3 * f + k];
                float dx = verts[3 * vi + 0] - ex;
                float dy = verts[3 * vi + 1] - ey;
                float dz = verts[3 * vi + 2] - ez;
                float cx = xx * dx + xz * dz;            // x.y == 0
                float cy = yx * dx + yy * dy + yz * dz;
                float cz = zx * dx + zy * dy + zz * dz;
                float zw = cz * w;
                px[k] = cx / zw;
                py[k] = cy / zw;
            }

            // area sign (no FMA contraction near exact zero)
            float e01x = px[1] - px[0], e01y = py[1] - py[0];
            float e02x = px[2] - px[0], e02y = py[2] - py[0];
            float area = __fmul_rn(e01x, e02y) - __fmul_rn(e01y, e02x);
            float s = (area > 0.f) ? 1.f : ((area < 0.f) ? -1.f : 0.f);

            // K = s * inv_sigma * log2(e); degenerate (s=0) -> coeffs 0 ->
            // frag = 0.125 uniformly (= sigmoid(0)^3), never culled.
            float K = s * 144.26950408889634f;  // 100 * log2(e)

            float A[3], B[3], C[3];
            const int ia[3] = {0, 1, 2}, ib[3] = {1, 2, 0};
            #pragma unroll
            for (int e = 0; e < 3; e++) {
                float ax = px[ib[e]] - px[ia[e]];
                float ay = py[ib[e]] - py[ia[e]];
                float len = sqrtf(ax*ax + ay*ay) + EPSF;
                float nx = -ay / len, ny = ax / len;
                A[e] = -K * nx;
                B[e] = -K * ny;
                C[e] =  K * (px[ia[e]] * nx + py[ia[e]] * ny);
            }
            fa = make_float4(A[0], B[0], C[0], A[1]);
            fb = make_float4(B[1], C[1], A[2], B[2]);
            fc = C[2];

            // conservative tile cull: keep iff max_e(min over tile of L'_e) < T
            float m0 = (fa.x > 0.f ? fa.x * xmin : fa.x * xmax)
                     + (fa.y > 0.f ? fa.y * ymin : fa.y * ymax) + fa.z;
            float m1 = (fa.w > 0.f ? fa.w * xmin : fa.w * xmax)
                     + (fb.x > 0.f ? fb.x * ymin : fb.x * ymax) + fb.y;
            float m2 = (fb.z > 0.f ? fb.z * xmin : fb.z * xmax)
                     + (fb.w > 0.f ? fb.w * ymin : fb.w * ymax) + fc;
            keep = fmaxf(m0, fmaxf(m1, m2)) < KEEP_T;
        }
    }
    unsigned bal = __ballot_sync(0xffffffffu, keep);
    if (lane == 0 && wid < 2) wcnt[wid] = __popc(bal);
    __syncthreads();

    int cnt = wcnt[0] + wcnt[1];
    if (keep) {
        int off = __popc(bal & ((1u << lane) - 1u)) + (wid == 1 ? wcnt[0] : 0);
        sA[off] = fa; sB[off] = fb; sC[off] = fc;
    }
    __syncthreads();

    // ---------------- Phase B: per-pixel partial product --------------------
    const int gc = c0 + (tid & 15);
    const int gr = r0 + (tid >> 4);
    const int pix = gr * IMG + gc;
    const float X = (2.f * gc + 1.f) * (1.f / 256.f) - 1.f;
    const float Y = 1.f - (2.f * gr + 1.f) * (1.f / 256.f);

    float prod = 1.f;
    for (int i = 0; i < cnt; i++) {
        float4 a = sA[i];
        float4 b = sB[i];
        float  cc = sC[i];
        float L0 = fmaf(a.x, X, fmaf(a.y, Y, a.z));
        float L1 = fmaf(a.w, X, fmaf(b.x, Y, b.y));
        float L2 = fmaf(b.z, X, fmaf(b.w, Y, cc));
        // frag = 1/((1+e0)(1+e1)(1+e2)); factors >= 1 -> no inf*0 NaN
        float u0 = 1.f + ex2f(L0);
        float u1 = 1.f + ex2f(L1);
        float u2 = 1.f + ex2f(L2);
        float P  = u0 * u1 * u2;
        float r  = rcpaf(P);          // = frag
        prod = fmaf(prod, -r, prod);  // prod *= (1 - frag)
    }
    g_part[z * (IMG * IMG) + pix] = prod;

    // ---------------- Phase C: last chunk for this tile combines ------------
    __threadfence();
    if (tid == 0) {
        unsigned old = atomicInc(&g_tcnt[tileIdx], SPLIT - 1);  // wraps -> replay-safe
        s_flag = (old == SPLIT - 1);
    }
    __syncthreads();
    if (!s_flag) return;

    __threadfence();  // acquire: see all 16 plane writes
    float p = 1.f;
    #pragma unroll
    for (int zz = 0; zz < SPLIT; zz++) p *= g_part[zz * (IMG * IMG) + pix];
    float sil = 1.f - p;
    float d = sil - ref[pix];
    red[tid] = d * d;
    __syncthreads();
    #pragma unroll
    for (int s2 = 128; s2 > 0; s2 >>= 1) {
        if (tid < s2) red[tid] += red[tid + s2];
        __syncthreads();
    }

    // ---------------- Phase D: last tile sums 256 tile losses ---------------
    if (tid == 0) {
        g_row[tileIdx] = red[0];
        __threadfence();
        unsigned old = atomicInc(&g_done, IMG - 1);  // wraps each replay
        s_flag = (old == IMG - 1);
    }
    __syncthreads();
    if (!s_flag) return;

    __threadfence();
    red[tid] = g_row[tid];
    __syncthreads();
    #pragma unroll
    for (int s2 = 128; s2 > 0; s2 >>= 1) {
        if (tid < s2) red[tid] += red[tid + s2];
        __syncthreads();
    }
    if (tid == 0) out[0] = red[0];
}

extern "C" void kernel_launch(void* const* d_in, const int* in_sizes, int n_in,
                              void* d_out, int out_size)
{
    const float* verts = (const float*)d_in[0];   // (1,502,3)
    const int*   faces = (const int*)  d_in[1];   // (1,1000,3)
    const float* cam   = (const float*)d_in[2];   // (3,)
    const float* ref   = (const float*)d_in[3];   // (1,256,256)

    dim3 grid(IMG / 16, IMG / 16, SPLIT);
    fused_kernel<<<grid, 256>>>(verts, faces, cam, ref, (float*)d_out);
}

// round 4
// speedup vs baseline: 1.1867x; 1.1867x over previous
#include <cuda_runtime.h>
#include <cstdint>

#define NFACES 1000
#define IMG    256
#define SPLIT  16
#define CHUNK  64                 // faces per chunk (16*64 = 1024 >= 1000)
#define CULL_T 25.5f              // sum-relu bound: frag < 2^-25.5 -> factor rounds away

__device__ float    g_part[SPLIT * IMG * IMG];  // per-chunk partial products (4 MB)
__device__ float    g_row[IMG];                 // per-tile loss sums
__device__ unsigned g_tcnt[IMG];                // per-tile chunk counters (wrapping -> replay-safe)
__device__ unsigned g_done;                     // tile-completion counter

__device__ __forceinline__ float ex2f(float x) {
    float y; asm("ex2.approx.f32 %0, %1;" : "=f"(y) : "f"(x)); return y;
}
__device__ __forceinline__ float rcpaf(float x) {
    float y; asm("rcp.approx.f32 %0, %1;" : "=f"(y) : "f"(x)); return y;
}
__device__ __forceinline__ float rsqaf(float x) {
    float y; asm("rsqrt.approx.f32 %0, %1;" : "=f"(y) : "f"(x)); return y;
}

// ---------------------------------------------------------------------------
// Single fused kernel: grid (16, 16, SPLIT), 256 threads.
//   Phase A: threads 0..63 prep this chunk's faces (approx math) +
//            sum-relu tile cull + degenerate extraction
//   Phase B: per-pixel partial soft-OR product (warp-level all-out skip)
//   Phase C: last chunk per tile combines 16 planes -> tile loss
//   Phase D: last tile sums 256 tile losses -> out[0]
// ---------------------------------------------------------------------------
__global__ void __launch_bounds__(256) fused_kernel(
    const float* __restrict__ verts,   // (1, V, 3)
    const int*   __restrict__ faces,   // (1, F, 3)
    const float* __restrict__ cam,     // (3,)
    const float* __restrict__ ref,     // (1, 256, 256)
    float*       __restrict__ out)
{
    __shared__ float4 sA[CHUNK], sB[CHUNK];
    __shared__ float  sC[CHUNK];
    __shared__ int    wcnt[2], wdeg[2];
    __shared__ int    s_flag;
    __shared__ float  red[256];

    const int tid  = threadIdx.x;
    const int lane = tid & 31, wid = tid >> 5;
    const int c0 = blockIdx.x * 16, r0 = blockIdx.y * 16;
    const int tileIdx = blockIdx.y * 16 + blockIdx.x;
    const int z = blockIdx.z;

    // tile pixel-center bounds (y decreases with row)
    const float xmin = (2.f * c0 + 1.f)        * (1.f / 256.f) - 1.f;
    const float xmax = (2.f * (c0 + 15) + 1.f) * (1.f / 256.f) - 1.f;
    const float ymax = 1.f - (2.f * r0 + 1.f)        * (1.f / 256.f);
    const float ymin = 1.f - (2.f * (r0 + 15) + 1.f) * (1.f / 256.f);

    // ---------------- Phase A: prep + cull + degenerate extraction ----------
    bool keep = false, deg = false;
    float4 fa = make_float4(0,0,0,0), fb = make_float4(0,0,0,0);
    float  fc = 0.f;

    if (tid < CHUNK) {
        int f = z * CHUNK + tid;
        if (f < NFACES) {
            float ex = cam[0], ey = cam[1], ez = cam[2];

            // camera basis (z = normalize(-eye), up = (0,1,0)); approx rsqrt
            float rz = rsqaf(ex*ex + ey*ey + ez*ez);
            float zx = -ex * rz, zy = -ey * rz, zz = -ez * rz;
            float rx = rsqaf(zz*zz + zx*zx);
            float xx = zz * rx, xz = -zx * rx;
            float yx = zy * xz;
            float yy = zz * xx - zx * xz;
            float yz = -zy * xx;

            const float w = 0.57735026918962576f;  // tan(30 deg)

            float px[3], py[3];
            #pragma unroll
            for (int k = 0; k < 3; k++) {
                int vi = faces[3 * f + k];
                float dx = verts[3 * vi + 0] - ex;
                float dy = verts[3 * vi + 1] - ey;
                float dz = verts[3 * vi + 2] - ez;
                float cx = xx * dx + xz * dz;            // x.y == 0
                float cy = yx * dx + yy * dy + yz * dz;
                float cz = zx * dx + zy * dy + zz * dz;
                float rzw = rcpaf(cz * w);
                px[k] = cx * rzw;
                py[k] = cy * rzw;
            }

            // area sign; exact-0 iff duplicate vertex indices (bitwise-equal proj)
            float e01x = px[1] - px[0], e01y = py[1] - py[0];
            float e02x = px[2] - px[0], e02y = py[2] - py[0];
            float area = __fmul_rn(e01x, e02y) - __fmul_rn(e01y, e02x);

            if (area == 0.f) {
                deg = true;   // frag = 0.125 everywhere -> analytic 0.875 factor
            } else {
                float s = (area > 0.f) ? 1.f : -1.f;
                float K = s * 144.26950408889634f;  // inv_sigma * log2(e)

                float A[3], B[3], C[3];
                const int ia[3] = {0, 1, 2}, ib[3] = {1, 2, 0};
                #pragma unroll
                for (int e = 0; e < 3; e++) {
                    float ax = px[ib[e]] - px[ia[e]];
                    float ay = py[ib[e]] - py[ia[e]];
                    float rlen = rsqaf(ax*ax + ay*ay);
                    float nx = -ay * rlen, ny = ax * rlen;
                    A[e] = -K * nx;
                    B[e] = -K * ny;
                    C[e] =  K * (px[ia[e]] * nx + py[ia[e]] * ny);
                }
                fa = make_float4(A[0], B[0], C[0], A[1]);
                fb = make_float4(B[1], C[1], A[2], B[2]);
                fc = C[2];

                // per-edge min over tile (affine -> corner by coeff signs)
                float m0 = (fa.x > 0.f ? fa.x * xmin : fa.x * xmax)
                         + (fa.y > 0.f ? fa.y * ymin : fa.y * ymax) + fa.z;
                float m1 = (fa.w > 0.f ? fa.w * xmin : fa.w * xmax)
                         + (fb.x > 0.f ? fb.x * ymin : fb.x * ymax) + fb.y;
                float m2 = (fb.z > 0.f ? fb.z * xmin : fb.z * xmax)
                         + (fb.w > 0.f ? fb.w * ymin : fb.w * ymax) + fc;
                // valid bound: frag <= 2^-(relu(m0)+relu(m1)+relu(m2)) everywhere in tile
                float q = fmaxf(m0, 0.f) + fmaxf(m1, 0.f) + fmaxf(m2, 0.f);
                keep = q < CULL_T;
            }
        }
    }
    unsigned balK = __ballot_sync(0xffffffffu, keep);
    unsigned balD = __ballot_sync(0xffffffffu, deg);
    if (lane == 0 && wid < 2) { wcnt[wid] = __popc(balK); wdeg[wid] = __popc(balD); }
    __syncthreads();

    int cnt  = wcnt[0] + wcnt[1];
    int ndeg = wdeg[0] + wdeg[1];
    if (keep) {
        int off = __popc(balK & ((1u << lane) - 1u)) + (wid == 1 ? wcnt[0] : 0);
        sA[off] = fa; sB[off] = fb; sC[off] = fc;
    }
    __syncthreads();

    // ---------------- Phase B: per-pixel partial product --------------------
    const int gc = c0 + (tid & 15);
    const int gr = r0 + (tid >> 4);
    const int pix = gr * IMG + gc;
    const float X = (2.f * gc + 1.f) * (1.f / 256.f) - 1.f;
    const float Y = 1.f - (2.f * gr + 1.f) * (1.f / 256.f);

    float prod = 1.f;
    for (int i = 0; i < cnt; i++) {
        float4 a = sA[i];
        float4 b = sB[i];
        float  cc = sC[i];
        float L0 = fmaf(a.x, X, fmaf(a.y, Y, a.z));
        float L1 = fmaf(a.w, X, fmaf(b.x, Y, b.y));
        float L2 = fmaf(b.z, X, fmaf(b.w, Y, cc));
        // frag <= 2^-(sum of relus): if every lane is saturated-out, skip MUFU
        float q = fmaxf(L0, 0.f) + fmaxf(L1, 0.f) + fmaxf(L2, 0.f);
        if (__all_sync(0xffffffffu, q >= CULL_T)) continue;
        // frag = 1/((1+e0)(1+e1)(1+e2)); factors >= 1 -> no inf*0 NaN
        float u0 = 1.f + ex2f(L0);
        float u1 = 1.f + ex2f(L1);
        float u2 = 1.f + ex2f(L2);
        float r  = rcpaf(u0 * u1 * u2);   // = frag
        prod = fmaf(prod, -r, prod);      // prod *= (1 - frag)
    }
    // degenerate faces: frag = 0.125 uniformly -> factor 0.875 each (exact)
    for (int i = 0; i < ndeg; i++) prod *= 0.875f;

    g_part[z * (IMG * IMG) + pix] = prod;

    // ---------------- Phase C: last chunk for this tile combines ------------
    __threadfence();
    if (tid == 0) {
        unsigned old = atomicInc(&g_tcnt[tileIdx], SPLIT - 1);  // wraps -> replay-safe
        s_flag = (old == SPLIT - 1);
    }
    __syncthreads();
    if (!s_flag) return;

    __threadfence();  // acquire: see all 16 plane writes
    float p = 1.f;
    #pragma unroll
    for (int zz = 0; zz < SPLIT; zz++) p *= g_part[zz * (IMG * IMG) + pix];
    float sil = 1.f - p;
    float d = sil - ref[pix];
    red[tid] = d * d;
    __syncthreads();
    #pragma unroll
    for (int s2 = 128; s2 > 0; s2 >>= 1) {
        if (tid < s2) red[tid] += red[tid + s2];
        __syncthreads();
    }

    // ---------------- Phase D: last tile sums 256 tile losses ---------------
    if (tid == 0) {
        g_row[tileIdx] = red[0];
        __threadfence();
        unsigned old = atomicInc(&g_done, IMG - 1);  // wraps each replay
        s_flag = (old == IMG - 1);
    }
    __syncthreads();
    if (!s_flag) return;

    __threadfence();
    red[tid] = g_row[tid];
    __syncthreads();
    #pragma unroll
    for (int s2 = 128; s2 > 0; s2 >>= 1) {
        if (tid < s2) red[tid] += red[tid + s2];
        __syncthreads();
    }
    if (tid == 0) out[0] = red[0];
}

extern "C" void kernel_launch(void* const* d_in, const int* in_sizes, int n_in,
                              void* d_out, int out_size)
{
    const float* verts = (const float*)d_in[0];   // (1,502,3)
    const int*   faces = (const int*)  d_in[1];   // (1,1000,3)
    const float* cam   = (const float*)d_in[2];   // (3,)
    const float* ref   = (const float*)d_in[3];   // (1,256,256)

    dim3 grid(IMG / 16, IMG / 16, SPLIT);
    fused_kernel<<<grid, 256>>>(verts, faces, cam, ref, (float*)d_out);
}